// round 12
// baseline (speedup 1.0000x reference)
#include <cuda_runtime.h>
#include <cuda_bf16.h>
#include <cstdint>

// LinAminoToAtom via mma.sync bf16 3-term split.
// R12: smem-transposed epilogue — D fragments -> os[32][100] -> coalesced
// float4 STG (replaces 24 scattered scalar STG/thread, ~10 sectors each).
// Mainloop (R11 fragment-reuse) and prep unchanged.

#define NODES 512
#define BATCH 64
#define AMINO 64
#define ATOMN 32
#define RMAXJ 416
#define LDA   272              // A smem row stride bytes
#define LDB   208              // B smem row stride bytes
#define A_ROWS 64              // M-tile rows (2 residues)
#define A_REGION (A_ROWS * LDA)   // 17408
#define B_REGION (128 * LDB)      // 26624
#define A_V4  (A_REGION / 16)     // 1088
#define NTILE_MAX 7
#define OSTR  100              // out-staging row stride (floats; 16B-aligned)
#define OS_BYTES (32 * OSTR * 4)  // 12800
#define SMEM_MAIN (2 * A_REGION + B_REGION + OS_BYTES)   // 74240 (3 CTAs/SM)

__constant__ int c_reslen[20] = {4,10,7,7,5,8,8,3,9,7,7,8,7,10,6,5,6,13,11,6};

__device__ int d_type[NODES];
__device__ int d_len[NODES];
__device__ int d_gbase[NODES];
__device__ uint4 d_Wprep[20 * NTILE_MAX * A_V4];   // per-(type,mtile) A image

// ---------------- helpers ----------------
__device__ __forceinline__ uint32_t smem_u32(const void* p) {
    uint32_t a;
    asm("{ .reg .u64 t; cvta.to.shared.u64 t, %1; cvt.u32.u64 %0, t; }"
        : "=r"(a) : "l"(p));
    return a;
}
__device__ __forceinline__ void bf16_split(float f, uint16_t& hb, uint16_t& lb) {
    __nv_bfloat16 h = __float2bfloat16_rn(f);
    float l = f - __bfloat162float(h);
    __nv_bfloat16 g = __float2bfloat16_rn(l);
    hb = __bfloat16_as_ushort(h);
    lb = __bfloat16_as_ushort(g);
}
#define LDSM_X4(r, a) \
    asm volatile("ldmatrix.sync.aligned.m8n8.x4.shared.b16 {%0,%1,%2,%3}, [%4];" \
        : "=r"((r)[0]), "=r"((r)[1]), "=r"((r)[2]), "=r"((r)[3]) : "r"(a))
#define LDSM_X4T(r, a) \
    asm volatile("ldmatrix.sync.aligned.m8n8.x4.trans.shared.b16 {%0,%1,%2,%3}, [%4];" \
        : "=r"((r)[0]), "=r"((r)[1]), "=r"((r)[2]), "=r"((r)[3]) : "r"(a))
#define LDSM_X2T(r, a) \
    asm volatile("ldmatrix.sync.aligned.m8n8.x2.trans.shared.b16 {%0,%1}, [%2];" \
        : "=r"((r)[0]), "=r"((r)[1]) : "r"(a))
__device__ __forceinline__ void mma_bf16(float* c, const uint32_t* a, const uint32_t* b) {
    asm volatile(
        "mma.sync.aligned.m16n8k16.row.col.f32.bf16.bf16.f32 "
        "{%0,%1,%2,%3}, {%4,%5,%6,%7}, {%8,%9}, {%0,%1,%2,%3};"
        : "+f"(c[0]), "+f"(c[1]), "+f"(c[2]), "+f"(c[3])
        : "r"(a[0]), "r"(a[1]), "r"(a[2]), "r"(a[3]), "r"(b[0]), "r"(b[1]));
}
#define CP_ASYNC16(dst, src) \
    asm volatile("cp.async.cg.shared.global [%0], [%1], 16;" :: "r"(dst), "l"(src))
#define CP_COMMIT() asm volatile("cp.async.commit_group;" ::: "memory")
#define CP_WAIT0()  asm volatile("cp.async.wait_group 0;" ::: "memory")

// ---------- prep: blocks 0..139 build W images; block 140 runs setup scan ----
__global__ void prep_kernel(const float* __restrict__ W,
                            const void* __restrict__ tids_raw) {
    __shared__ char Aimg[A_REGION];
    __shared__ int wsum[16];
    __shared__ int flag64;
    const int bx  = blockIdx.x;
    const int tid = threadIdx.x;

    if (bx == 20 * NTILE_MAX) {
        const int* s32 = (const int*)tids_raw;
        int n = tid;
        if (n == 0) flag64 = 1;
        __syncthreads();
        if (n < 256) {
            int lo = s32[2 * n], hi = s32[2 * n + 1];
            if (hi != 0 || (unsigned)lo >= 20u) atomicAnd(&flag64, 0);
        }
        __syncthreads();
        int t = flag64 ? s32[2 * n] : s32[n];
        int l = c_reslen[t];
        d_type[n] = t;
        d_len[n]  = l;
        int lane = n & 31, wid = n >> 5;
        int v = l;
#pragma unroll
        for (int off = 1; off < 32; off <<= 1) {
            int u = __shfl_up_sync(0xffffffffu, v, off);
            if (lane >= off) v += u;
        }
        if (lane == 31) wsum[wid] = v;
        __syncthreads();
        if (wid == 0 && lane < 16) {
            int s = wsum[lane];
#pragma unroll
            for (int off = 1; off < 16; off <<= 1) {
                int u = __shfl_up_sync(0x0000ffffu, s, off);
                if (lane >= off) s += u;
            }
            wsum[lane] = s;
        }
        __syncthreads();
        d_gbase[n] = v - l + (wid > 0 ? wsum[wid - 1] : 0);
        return;
    }

    const int t  = bx / NTILE_MAX;
    const int mt = bx % NTILE_MAX;
    const int jw = tid & 63, ae = tid >> 6;
    const int jmax = c_reslen[t] * ATOMN;
    const float* Wt = W + (size_t)t * AMINO * RMAXJ;
    {
        int jg = mt * A_ROWS + jw;
        bool val = jg < jmax;
        uint32_t hp[4], lp[4];
#pragma unroll
        for (int q = 0; q < 4; ++q) {
            int a = ae * 8 + 2 * q;
            float w0 = val ? Wt[(size_t)a * RMAXJ + jg] : 0.0f;
            float w1 = val ? Wt[(size_t)(a + 1) * RMAXJ + jg] : 0.0f;
            uint16_t hb0, lb0, hb1, lb1;
            bf16_split(w0, hb0, lb0);
            bf16_split(w1, hb1, lb1);
            hp[q] = (uint32_t)hb0 | ((uint32_t)hb1 << 16);
            lp[q] = (uint32_t)lb0 | ((uint32_t)lb1 << 16);
        }
        char* rowp = Aimg + jw * LDA + ae * 16;
        *reinterpret_cast<uint4*>(rowp)       = make_uint4(hp[0], hp[1], hp[2], hp[3]);
        *reinterpret_cast<uint4*>(rowp + 128) = make_uint4(lp[0], lp[1], lp[2], lp[3]);
    }
    __syncthreads();
    uint4* dst = d_Wprep + (size_t)bx * A_V4;
    const uint4* src = (const uint4*)Aimg;
    for (int i = tid; i < A_V4; i += 512) dst[i] = src[i];
}

// ---------- main ----------
__global__ void __launch_bounds__(256, 3)
lin_amino_kernel(const float* __restrict__ x, float* __restrict__ out, int G) {
    extern __shared__ char smem[];
    const int tid  = threadIdx.x;
    const int warp = tid >> 5;
    const int lane = tid & 31;
    const int bx   = blockIdx.x;
    const int n    = bx >> 1;
    const int half = bx & 1;
    const int t    = d_type[n];
    const int len  = d_len[n];
    const int gb   = d_gbase[n];
    const int ntiles = (len + 1) >> 1;

    const uint32_t Abase = smem_u32(smem);
    const uint32_t Bsm   = Abase + 2 * A_REGION;
    char*  Bp  = smem + 2 * A_REGION;
    float* osp = (float*)(smem + 2 * A_REGION + B_REGION);

    // ---- A tile 0 cp.async (overlaps X convert) ----
    {
        const char* asrc = (const char*)(d_Wprep + (size_t)(t * NTILE_MAX) * A_V4);
        for (int i = tid; i < A_V4; i += 256)
            CP_ASYNC16(Abase + i * 16, asrc + i * 16);
        CP_COMMIT();
    }

    // ---- X convert: direct LDG + split -> B smem (rows a=Xh, 64+a=Xl) ----
    for (int i = tid; i < AMINO * 32; i += 256) {
        int a = i & 63, bl = i >> 6;
        const float* s = x + ((size_t)(half * 32 + bl) * NODES + n) * 192 + a * 3;
        uint16_t h0, l0, h1, l1, h2, l2;
        bf16_split(s[0], h0, l0);
        bf16_split(s[1], h1, l1);
        bf16_split(s[2], h2, l2);
        char* rh = Bp + a * LDB + bl * 6;
        char* rl = rh + 64 * LDB;
        *(uint16_t*)(rh + 0) = h0; *(uint16_t*)(rh + 2) = h1; *(uint16_t*)(rh + 4) = h2;
        *(uint16_t*)(rl + 0) = l0; *(uint16_t*)(rl + 2) = l1; *(uint16_t*)(rl + 4) = l2;
    }

    const int m_block = (warp & 1) * 32;    // warp&1 = residue within tile
    const int n_block = (warp >> 1) * 24;   // 3 n-frags of 8
    const int l15 = lane & 15, lh = lane >> 4;
    const uint32_t aoff_lane = (uint32_t)(m_block + l15) * LDA + lh * 16;
    const uint32_t bbase4 = Bsm + (uint32_t)l15 * LDB + (uint32_t)(n_block + lh * 8) * 2;
    const uint32_t bbase2 = Bsm + (uint32_t)l15 * LDB + (uint32_t)(n_block + 16) * 2;

    const size_t Gs = (size_t)G * 96;
    float* out_half = out + (size_t)(half * 32) * Gs;

    for (int mt = 0; mt < ntiles; ++mt) {
        CP_WAIT0();
        __syncthreads();

        // ---- prefetch next A tile: overlaps whole mainloop ----
        if (mt + 1 < ntiles) {
            const uint32_t Anext = Abase + (uint32_t)((mt + 1) & 1) * A_REGION;
            const char* asrc =
                (const char*)(d_Wprep + (size_t)(t * NTILE_MAX + mt + 1) * A_V4);
            for (int i = tid; i < A_V4; i += 256)
                CP_ASYNC16(Anext + i * 16, asrc + i * 16);
            CP_COMMIT();
        }

        const uint32_t Acur = Abase + (uint32_t)(mt & 1) * A_REGION;
        const uint32_t aaddr0 = Acur + aoff_lane;
        const uint32_t aaddr1 = aaddr0 + 16 * LDA;

        // ---- mainloop: 4 kk-steps; per kk load Wh,Wl,Xh,Xl once, 18 MMAs ----
        float acc[2][3][4];
#pragma unroll
        for (int i = 0; i < 2; ++i)
#pragma unroll
            for (int j = 0; j < 3; ++j)
#pragma unroll
                for (int k = 0; k < 4; ++k) acc[i][j][k] = 0.0f;

#pragma unroll
        for (int kk = 0; kk < 4; ++kk) {
            const uint32_t koff = (uint32_t)kk * 32;
            const uint32_t bo   = (uint32_t)(kk * 16) * LDB;
            uint32_t aWh0[4], aWh1[4], aWl0[4], aWl1[4];
            LDSM_X4(aWh0, aaddr0 + koff);
            LDSM_X4(aWh1, aaddr1 + koff);
            LDSM_X4(aWl0, aaddr0 + 128 + koff);
            LDSM_X4(aWl1, aaddr1 + 128 + koff);
            uint32_t bh01[4], bh2[2], bl01[4], bl2[2];
            LDSM_X4T(bh01, bbase4 + bo);
            LDSM_X2T(bh2,  bbase2 + bo);
            LDSM_X4T(bl01, bbase4 + 64 * LDB + bo);
            LDSM_X2T(bl2,  bbase2 + 64 * LDB + bo);
            mma_bf16(acc[0][0], aWh0, bh01);     mma_bf16(acc[1][0], aWh1, bh01);
            mma_bf16(acc[0][1], aWh0, bh01 + 2); mma_bf16(acc[1][1], aWh1, bh01 + 2);
            mma_bf16(acc[0][2], aWh0, bh2);      mma_bf16(acc[1][2], aWh1, bh2);
            mma_bf16(acc[0][0], aWl0, bh01);     mma_bf16(acc[1][0], aWl1, bh01);
            mma_bf16(acc[0][1], aWl0, bh01 + 2); mma_bf16(acc[1][1], aWl1, bh01 + 2);
            mma_bf16(acc[0][2], aWl0, bh2);      mma_bf16(acc[1][2], aWl1, bh2);
            mma_bf16(acc[0][0], aWh0, bl01);     mma_bf16(acc[1][0], aWh1, bl01);
            mma_bf16(acc[0][1], aWh0, bl01 + 2); mma_bf16(acc[1][1], aWh1, bl01 + 2);
            mma_bf16(acc[0][2], aWh0, bl2);      mma_bf16(acc[1][2], aWh1, bl2);
        }

        // ---- epilogue: smem transpose then coalesced float4 stores ----
        const int row0 = lane >> 2, npair = (lane & 3) * 2;
#pragma unroll
        for (int res = 0; res < 2; ++res) {
            int r_idx = mt * 2 + res;            // block-uniform
            bool have = (r_idx < len);
            if (have && (warp & 1) == res) {
#pragma unroll
                for (int mi = 0; mi < 2; ++mi) {
#pragma unroll
                    for (int nf = 0; nf < 3; ++nf) {
                        int n0 = n_block + nf * 8 + npair;
                        int b0 = n0 / 3, v0 = n0 - 3 * b0;
                        int n1 = n0 + 1;
                        int b1 = n1 / 3, v1 = n1 - 3 * b1;
                        int atomA = mi * 16 + row0;
                        int atomB = atomA + 8;
                        const float* c = acc[mi][nf];
                        osp[b0 * OSTR + atomA * 3 + v0] = c[0];
                        osp[b1 * OSTR + atomA * 3 + v1] = c[1];
                        osp[b0 * OSTR + atomB * 3 + v0] = c[2];
                        osp[b1 * OSTR + atomB * 3 + v1] = c[3];
                    }
                }
            }
            __syncthreads();
            if (have) {
                float* og = out_half + (size_t)(gb + r_idx) * 96;
                for (int f4 = tid; f4 < 32 * 24; f4 += 256) {
                    int b2 = f4 / 24, c4 = f4 % 24;
                    float4 v = *reinterpret_cast<const float4*>(
                        osp + b2 * OSTR + c4 * 4);
                    *reinterpret_cast<float4*>(og + (size_t)b2 * Gs + c4 * 4) = v;
                }
            }
            __syncthreads();
        }
    }
}

extern "C" void kernel_launch(void* const* d_in, const int* in_sizes, int n_in,
                              void* d_out, int out_size) {
    const float* x    = (const float*)d_in[0];
    const float* W    = (const float*)d_in[1];
    const void*  tids = d_in[2];
    float*       out  = (float*)d_out;

    int G = in_sizes[3];

    cudaFuncSetAttribute(lin_amino_kernel,
                         cudaFuncAttributeMaxDynamicSharedMemorySize, SMEM_MAIN);

    prep_kernel<<<20 * NTILE_MAX + 1, 512>>>(W, tids);
    lin_amino_kernel<<<NODES * 2, 256, SMEM_MAIN>>>(x, out, G);
}